// round 1
// baseline (speedup 1.0000x reference)
#include <cuda_runtime.h>
#include <cuda_bf16.h>

#define NB    32          // batches
#define NPTS  2048        // N == M
#define TPB   128         // threads per block
#define RPT   4           // rows per thread (register blocking)
#define ROWS_PER_BLOCK (TPB * RPT)   // 512
#define TILE  128         // column points per shared tile (== TPB)
#define BIGSQ 1.0e16f     // BIG^2 sentinel for masked columns

__global__ void chamfer_zero_kernel(float* out) {
    if (threadIdx.x < NB) out[threadIdx.x] = 0.0f;
}

__global__ __launch_bounds__(TPB) void chamfer_kernel(
    const int*   __restrict__ o_w,   const float* __restrict__ o_pts,
    const int*   __restrict__ t_w,   const float* __restrict__ t_pts,
    float*       __restrict__ out)
{
    const int b   = blockIdx.x;
    const int dir = blockIdx.z;

    // dir 0: rows = outputs, cols = targets   (row-min term, min over M)
    // dir 1: rows = targets, cols = outputs   (col-min term, min over N)
    const int*   rmask = dir ? t_w   : o_w;
    const float* rpts  = dir ? t_pts : o_pts;
    const int*   cmask = dir ? o_w   : t_w;
    const float* cpts  = dir ? o_pts : t_pts;

    __shared__ float sx[TILE], sy[TILE], sz[TILE], s2[TILE];

    const int tid  = threadIdx.x;
    const int row0 = blockIdx.y * ROWS_PER_BLOCK;

    // Register-resident row state: premultiplied -2*coords, |r|^2, mask, running min of (t^2 - 2 a.b)
    float m2x[RPT], m2y[RPT], m2z[RPT], r2[RPT], wr[RPT], rmin[RPT];

    #pragma unroll
    for (int k = 0; k < RPT; k++) {
        int n = row0 + k * TPB + tid;
        const float* p = rpts + ((size_t)b * NPTS + n) * 3;
        float x = p[0], y = p[1], z = p[2];
        m2x[k] = -2.0f * x;
        m2y[k] = -2.0f * y;
        m2z[k] = -2.0f * z;
        r2[k]  = x * x + y * y + z * z;
        wr[k]  = (float)rmask[b * NPTS + n];
        rmin[k] = 3.4e38f;
    }

    for (int m0 = 0; m0 < NPTS; m0 += TILE) {
        __syncthreads();
        {
            // one column point per thread (TPB == TILE)
            int m = m0 + tid;
            const float* p = cpts + ((size_t)b * NPTS + m) * 3;
            int w = cmask[b * NPTS + m];
            float x = p[0], y = p[1], z = p[2];
            if (!w) { x = 0.0f; y = 0.0f; z = 0.0f; }
            sx[tid] = x;
            sy[tid] = y;
            sz[tid] = z;
            s2[tid] = w ? (x * x + y * y + z * z) : BIGSQ;  // masked cols lose every min
        }
        __syncthreads();

        #pragma unroll 16
        for (int j = 0; j < TILE; j++) {
            float tx = sx[j], ty = sy[j], tz = sz[j], c = s2[j];
            #pragma unroll
            for (int k = 0; k < RPT; k++) {
                float s = fmaf(m2x[k], tx, c);
                s = fmaf(m2y[k], ty, s);
                s = fmaf(m2z[k], tz, s);
                rmin[k] = fminf(rmin[k], s);
            }
        }
    }

    // d2 = max(r2 + min(t2 - 2ab), 0) * row_mask  (matches reference's clamp + mask)
    float acc = 0.0f;
    #pragma unroll
    for (int k = 0; k < RPT; k++) {
        float d2 = fmaxf(r2[k] + rmin[k], 0.0f);
        acc += d2 * wr[k];
    }

    // block reduction: warp shuffles then cross-warp via shared
    __shared__ float red[TPB / 32];
    #pragma unroll
    for (int o = 16; o > 0; o >>= 1)
        acc += __shfl_down_sync(0xffffffffu, acc, o);
    if ((tid & 31) == 0) red[tid >> 5] = acc;
    __syncthreads();
    if (tid < (TPB / 32)) {
        acc = red[tid];
        #pragma unroll
        for (int o = (TPB / 64); o > 0; o >>= 1)
            acc += __shfl_down_sync((1u << (TPB / 32)) - 1u, acc, o);
        if (tid == 0) atomicAdd(&out[b], 0.5f * acc);
    }
}

extern "C" void kernel_launch(void* const* d_in, const int* in_sizes, int n_in,
                              void* d_out, int out_size) {
    const int*   o_w   = (const int*)  d_in[0];   // o_weights [32, 2048] int32
    const float* o_pts = (const float*)d_in[1];   // outputs   [32, 2048, 3] f32
    const int*   t_w   = (const int*)  d_in[2];   // t_weights [32, 2048] int32
    const float* t_pts = (const float*)d_in[3];   // targets   [32, 2048, 3] f32
    float* out = (float*)d_out;                   // [32] f32

    chamfer_zero_kernel<<<1, 32>>>(out);
    dim3 grid(NB, NPTS / ROWS_PER_BLOCK, 2);      // (32, 4, 2) = 256 blocks
    chamfer_kernel<<<grid, TPB>>>(o_w, o_pts, t_w, t_pts, out);
}